// round 6
// baseline (speedup 1.0000x reference)
#include <cuda_runtime.h>
#include <cuda_bf16.h>
#include <math.h>
#include <stdint.h>

// Problem constants
#define BB 4
#define BN 512
#define BH 32
#define NROWS 2048

// ---------------- scratch (static device globals; no allocs) ----------------
__device__ float g_Q [NROWS*64];
__device__ float g_K [NROWS*64];   // pre-scaled by DH^-0.5
__device__ float g_V [NROWS*64];
__device__ float g_Q2[NROWS*64];
__device__ float g_K2[NROWS*64];   // pre-scaled
__device__ float g_WE2T[64*64];    // W_E2^T : [hk][d]
__device__ float g_scores[(size_t)BH*BN*BN];  // 33.5 MB
__device__ unsigned g_maxbits[BH];
__device__ float g_hatt[NROWS*64];

// ---------------- helpers ----------------
__device__ __forceinline__ uint32_t smem_u32(const void* p) {
    uint32_t a;
    asm("{ .reg .u64 t; cvta.to.shared.u64 t, %1; cvt.u32.u64 %0, t; }" : "=r"(a) : "l"(p));
    return a;
}
__device__ __forceinline__ void mma_bf16(float c[4],
    uint32_t a0, uint32_t a1, uint32_t a2, uint32_t a3,
    uint32_t b0, uint32_t b1)
{
    asm volatile(
        "mma.sync.aligned.m16n8k16.row.col.f32.bf16.bf16.f32 "
        "{%0,%1,%2,%3}, {%4,%5,%6,%7}, {%8,%9}, {%0,%1,%2,%3};"
        : "+f"(c[0]), "+f"(c[1]), "+f"(c[2]), "+f"(c[3])
        : "r"(a0), "r"(a1), "r"(a2), "r"(a3), "r"(b0), "r"(b1));
}
__device__ __forceinline__ uint32_t packbf(float x, float y) {
    __nv_bfloat162 v = __floats2bfloat162_rn(x, y);
    return *(uint32_t*)&v;
}
__device__ __forceinline__ unsigned f2key(float f) {
    unsigned u = __float_as_uint(f);
    return (u & 0x80000000u) ? ~u : (u | 0x80000000u);
}
__device__ __forceinline__ float key2f(unsigned key) {
    unsigned u = (key & 0x80000000u) ? (key ^ 0x80000000u) : ~key;
    return __uint_as_float(u);
}
#define CPASYNC16(dst, src) \
    asm volatile("cp.async.cg.shared.global [%0], [%1], 16;" :: "r"(dst), "l"(src))
#define CPCOMMIT() asm volatile("cp.async.commit_group;" ::: "memory")

// ---------------- K0: init max accumulators + transpose W_E2 ----------------
__global__ void __launch_bounds__(256) k0_init(const float* __restrict__ WE2) {
    int t = threadIdx.x;
    if (t < BH) g_maxbits[t] = 0u;  // key-space -inf
    for (int i = t; i < 4096; i += 256) {
        int d = i >> 6, c = i & 63;
        g_WE2T[c*64 + d] = WE2[i];
    }
}

// ---------------- K1: x = LN(h+p); Q,K,V,Q2,K2 projections ----------------
__global__ void __launch_bounds__(64) k1_proj(
    const float* __restrict__ h, const float* __restrict__ p,
    const float* __restrict__ g1, const float* __restrict__ b1,
    const float* __restrict__ WQ, const float* __restrict__ WK,
    const float* __restrict__ WV, const float* __restrict__ WQ2,
    const float* __restrict__ WK2)
{
    int row = blockIdx.x;
    int t = threadIdx.x;
    __shared__ float xs[64];
    __shared__ float red[4];

    float v = h[row*64 + t] + p[row*64 + t];
    float s = v, sq = v*v;
    #pragma unroll
    for (int off = 16; off; off >>= 1) {
        s  += __shfl_down_sync(0xffffffffu, s,  off);
        sq += __shfl_down_sync(0xffffffffu, sq, off);
    }
    int wid = t >> 5, lane = t & 31;
    if (lane == 0) { red[wid*2] = s; red[wid*2+1] = sq; }
    __syncthreads();
    float S  = red[0] + red[2];
    float SQ = red[1] + red[3];
    float mean = S * (1.f/64.f);
    float var  = SQ * (1.f/64.f) - mean*mean;
    float rinv = rsqrtf(var + 1e-5f);
    xs[t] = (v - mean) * rinv * g1[t] + b1[t];
    __syncthreads();

    float q = 0.f, k = 0.f, vv = 0.f, q2 = 0.f, k2 = 0.f;
    #pragma unroll 8
    for (int d = 0; d < 64; ++d) {
        float x = xs[d];
        q  += x * WQ [d*64 + t];
        k  += x * WK [d*64 + t];
        vv += x * WV [d*64 + t];
        q2 += x * WQ2[d*64 + t];
        k2 += x * WK2[d*64 + t];
    }
    const float sc = 0.35355339059327373f;  // 8^-0.5
    g_Q [row*64 + t] = q;
    g_K [row*64 + t] = k * sc;
    g_V [row*64 + t] = vv;
    g_Q2[row*64 + t] = q2;
    g_K2[row*64 + t] = k2 * sc;
}

// ---------------- K2: cp.async pipelined bf16-mma fused scores + max ----------
// Block = one (b,i), 128 threads = 4 warps, 8 j-tiles of 64, double buffered.
// smem byte layout:
//   [0,34816)      e fp32 [2][64][68]
//   [34816,69632)  K2 fp32 [2][64][68]
//   [69632,+256)   qs; [69888,+256) q2s; [70144,+512) adjw[2][64]
//   [70656,+64) adjf; [70720,+256) lst; [70976,+4) cnt; [70980,+32) maxsh
#define K2OFFB 34816
#define QSOFF  69632
#define Q2SOFF 69888
#define ADJWOFF 70144
#define ADJFOFF 70656
#define LSTOFF  70720
#define CNTOFF  70976
#define MAXOFF  70980
#define K2_SMEM 71040

__global__ void __launch_bounds__(128) k2_scores(
    const float* __restrict__ e, const unsigned* __restrict__ adj,
    const float* __restrict__ WE)
{
    extern __shared__ char sm[];
    float* ef  = (float*)sm;                      // [2][4352]
    float* kf  = (float*)(sm + K2OFFB);           // [2][4352]
    float* qs  = (float*)(sm + QSOFF);
    float* q2s = (float*)(sm + Q2SOFF);
    unsigned* adjw = (unsigned*)(sm + ADJWOFF);   // [2][64]
    unsigned char* adjf = (unsigned char*)(sm + ADJFOFF);
    int* lst = (int*)(sm + LSTOFF);
    int* cnt = (int*)(sm + CNTOFF);
    unsigned* maxsh = (unsigned*)(sm + MAXOFF);
    const uint32_t sb = smem_u32(sm);

    int bi = blockIdx.x;
    int b = bi >> 9, i = bi & 511;
    int t = threadIdx.x;
    int w = t >> 5, lane = t & 31;
    int r = lane >> 2, cq = lane & 3;
    int m0 = w * 16;

    const float* ebase  = e + (size_t)bi * 512 * 64;
    const float* k2base = g_K2 + (size_t)b * 512 * 64;
    const unsigned* abase = adj + (size_t)bi * 512;

    // ---- tile prefetch (16KB e + 16KB K2 + 256B adj) ----
    auto prefetch = [&](int j0, int pb) {
        #pragma unroll
        for (int it = 0; it < 8; ++it) {
            int c = t + it*128;
            int jl = c >> 4, c4 = c & 15;
            uint32_t off = (uint32_t)(pb*17408 + (jl*68 + c4*4)*4);
            const float* gs = ebase + (size_t)(j0 + jl)*64 + c4*4;
            CPASYNC16(sb + off, gs);
            CPASYNC16(sb + K2OFFB + off, k2base + (size_t)(j0 + jl)*64 + c4*4);
        }
        if (t < 16)
            CPASYNC16(sb + ADJWOFF + pb*256 + t*16, abase + j0 + t*4);
        CPCOMMIT();
    };

    prefetch(0, 0);

    if (t < 64) qs[t] = g_Q[bi*64 + t];
    else        q2s[t-64] = g_Q2[bi*64 + (t-64)];
    if (t < 8) maxsh[t] = 0u;
    if (t == 0) *cnt = 0;
    __syncthreads();

    // ---- B fragments in registers (constant across tiles) ----
    uint32_t bf0[8][4], bf1[8][4];
    #pragma unroll
    for (int nt = 0; nt < 8; ++nt) {
        int n = nt*8 + r;
        float qv = q2s[n];
        #pragma unroll
        for (int kc = 0; kc < 4; ++kc) {
            const float* wp = &g_WE2T[n*64 + kc*16 + cq*2];
            float2 wa = *(const float2*)wp;
            float2 wb = *(const float2*)(wp + 8);
            bf0[nt][kc] = packbf(wa.x*qv, wa.y*qv);
            bf1[nt][kc] = packbf(wb.x*qv, wb.y*qv);
        }
    }

    float mh[8];
    #pragma unroll
    for (int x = 0; x < 8; ++x) mh[x] = -INFINITY;

    int buf = 0;
    for (int tt = 0; tt < 8; ++tt) {
        int j0 = tt * 64;
        if (tt > 0 && t == 0) *cnt = 0;
        if (tt < 7) prefetch(j0 + 64, buf ^ 1);
        if (tt < 7) asm volatile("cp.async.wait_group 1;" ::: "memory");
        else        asm volatile("cp.async.wait_group 0;" ::: "memory");
        __syncthreads();

        const float* es = ef + buf*4352;
        const float* ks = kf + buf*4352;

        if (t < 64) {
            unsigned a = adjw[buf*64 + t];
            adjf[t] = a ? 1 : 0;
            if (a) { int pos = atomicAdd(cnt, 1); lst[pos] = t; }
        }

        // ---- dense mma: 16 rows x 64 n per warp, K=64 ----
        float acc[8][4];
        #pragma unroll
        for (int nt = 0; nt < 8; ++nt)
            #pragma unroll
            for (int z = 0; z < 4; ++z) acc[nt][z] = 0.f;

        #pragma unroll
        for (int kc = 0; kc < 4; ++kc) {
            int col = kc*16 + cq*2;
            float2 f0 = *(const float2*)&es[(m0+r  )*68 + col];
            float2 f1 = *(const float2*)&es[(m0+r+8)*68 + col];
            float2 f2 = *(const float2*)&es[(m0+r  )*68 + col + 8];
            float2 f3 = *(const float2*)&es[(m0+r+8)*68 + col + 8];
            uint32_t a0 = packbf(f0.x, f0.y);
            uint32_t a1 = packbf(f1.x, f1.y);
            uint32_t a2 = packbf(f2.x, f2.y);
            uint32_t a3 = packbf(f3.x, f3.y);
            #pragma unroll
            for (int nt = 0; nt < 8; ++nt)
                mma_bf16(acc[nt], a0, a1, a2, a3, bf0[nt][kc], bf1[nt][kc]);
        }
        __syncthreads();   // adjf/lst/cnt ready

        // ---- epilogue: score[h,j] = <Y[j,h*8..], K2[j,h*8..]>, track max ----
        int jl0 = m0 + r, jl1 = jl0 + 8;
        #pragma unroll
        for (int h = 0; h < 8; ++h) {
            float2 ka = *(const float2*)&ks[jl0*68 + h*8 + 2*cq];
            float2 kb = *(const float2*)&ks[jl1*68 + h*8 + 2*cq];
            float s0 = acc[h][0]*ka.x + acc[h][1]*ka.y;
            float s1 = acc[h][2]*kb.x + acc[h][3]*kb.y;
            s0 += __shfl_xor_sync(0xffffffffu, s0, 1);
            s0 += __shfl_xor_sync(0xffffffffu, s0, 2);
            s1 += __shfl_xor_sync(0xffffffffu, s1, 1);
            s1 += __shfl_xor_sync(0xffffffffu, s1, 2);
            bool d0 = !adjf[jl0], d1 = !adjf[jl1];
            if (d0) mh[h] = fmaxf(mh[h], s0);
            if (d1) mh[h] = fmaxf(mh[h], s1);
            if (cq == 0) {
                size_t srow = ((size_t)(b*8 + h)*512 + i)*512 + j0;
                if (d0) g_scores[srow + jl0] = s0;
                if (d1) g_scores[srow + jl1] = s1;
            }
        }

        // ---- sparse E path: one adj column per warp ----
        int n = *cnt;
        for (int q = w; q < n; q += 4) {
            int jl = lst[q];
            int j = j0 + jl;
            float y0 = 0.f, y1 = 0.f;
            #pragma unroll 8
            for (int d = 0; d < 64; ++d) {
                float ev = es[jl*68 + d];
                y0 += ev * WE[d*64 + lane];
                y1 += ev * WE[d*64 + 32 + lane];
            }
            y0 *= qs[lane];
            y1 *= qs[lane + 32];
            const float* kp = &g_K[((size_t)(b*512 + j))*64];
            float z0 = y0 * kp[lane];
            float z1 = y1 * kp[lane + 32];
            z0 += __shfl_xor_sync(0xffffffffu, z0, 1);
            z0 += __shfl_xor_sync(0xffffffffu, z0, 2);
            z0 += __shfl_xor_sync(0xffffffffu, z0, 4);
            z1 += __shfl_xor_sync(0xffffffffu, z1, 1);
            z1 += __shfl_xor_sync(0xffffffffu, z1, 2);
            z1 += __shfl_xor_sync(0xffffffffu, z1, 4);
            if ((lane & 7) == 0) {
                int h0 = lane >> 3;
                g_scores[((size_t)(b*8 + h0    )*512 + i)*512 + j] = z0;
                g_scores[((size_t)(b*8 + h0 + 4)*512 + i)*512 + j] = z1;
                atomicMax(&maxsh[h0    ], f2key(z0));
                atomicMax(&maxsh[h0 + 4], f2key(z1));
            }
        }
        __syncthreads();   // buffers + lists free for reuse
        buf ^= 1;
    }

    // ---- fold per-thread dense maxes, publish ----
    #pragma unroll
    for (int h = 0; h < 8; ++h) {
        float m = mh[h];
        #pragma unroll
        for (int o = 16; o; o >>= 1) m = fmaxf(m, __shfl_xor_sync(0xffffffffu, m, o));
        if (lane == 0) atomicMax(&maxsh[h], f2key(m));
    }
    __syncthreads();
    if (t < 8) atomicMax(&g_maxbits[b*8 + t], maxsh[t]);
}

// ---------------- K4: exp/mask/k_RW + rowsum + att@V ----------------
__global__ void __launch_bounds__(256) k4_att(
    const float* __restrict__ kRW, const float* __restrict__ mask)
{
    extern __shared__ float Vs[];  // [64][513]
    __shared__ float msk[512];
    int b  = blockIdx.y;
    int i0 = blockIdx.x * 8;
    int t = threadIdx.x, lane = t & 31, h = t >> 5;

    for (int idx = t; idx < BN*64; idx += 256) {
        int j = idx >> 6, c = idx & 63;
        Vs[c*513 + j] = g_V[((size_t)(b*BN + j))*64 + c];
    }
    for (int j = t; j < 512; j += 256) msk[j] = mask[b*512 + j];
    __syncthreads();

    float mx = key2f(g_maxbits[b*8 + h]);

    for (int ii = 0; ii < 8; ++ii) {
        int i = i0 + ii;
        float mi = msk[i];
        const float* sp = g_scores + ((size_t)(b*8 + h)*BN + i)*BN;
        const float* wp = kRW + ((size_t)(b*BN + i))*BN;
        float pden = 0.f;
        float pav[8];
        #pragma unroll
        for (int k = 0; k < 8; ++k) pav[k] = 0.f;

        for (int jt = 0; jt < 16; ++jt) {
            int j = jt*32 + lane;
            float pw = __expf(sp[j] - mx) * wp[j] * msk[j] * mi;
            pden += pw;
            #pragma unroll
            for (int k = 0; k < 8; ++k) pav[k] += pw * Vs[(h*8 + k)*513 + j];
        }
        #pragma unroll
        for (int off = 16; off; off >>= 1) {
            pden += __shfl_down_sync(0xffffffffu, pden, off);
            #pragma unroll
            for (int k = 0; k < 8; ++k) pav[k] += __shfl_down_sync(0xffffffffu, pav[k], off);
        }
        if (lane == 0) {
            float inv = 1.f / fmaxf(pden, 1e-6f);
            float4* op = (float4*)&g_hatt[((size_t)(b*BN + i))*64 + h*8];
            op[0] = make_float4(pav[0]*inv, pav[1]*inv, pav[2]*inv, pav[3]*inv);
            op[1] = make_float4(pav[4]*inv, pav[5]*inv, pav[6]*inv, pav[7]*inv);
        }
    }
}

// ---------------- K5: O-proj + residual + LN2 + FFN + residual ----------------
__global__ void __launch_bounds__(64) k5_out(
    const float* __restrict__ hin, const float* __restrict__ OW,
    const float* __restrict__ Ob, const float* __restrict__ g2,
    const float* __restrict__ b2, const float* __restrict__ Wf1,
    const float* __restrict__ bf1, const float* __restrict__ Wf2,
    const float* __restrict__ bf2, float* __restrict__ out)
{
    int row = blockIdx.x;
    int t = threadIdx.x;
    __shared__ float has[64], ys[64], hid[128];
    __shared__ float red[4];

    has[t] = g_hatt[row*64 + t];
    __syncthreads();

    float a = hin[row*64 + t] + Ob[t];
    #pragma unroll 8
    for (int d = 0; d < 64; ++d) a += has[d] * OW[d*64 + t];

    float s = a, sq = a*a;
    #pragma unroll
    for (int off = 16; off; off >>= 1) {
        s  += __shfl_down_sync(0xffffffffu, s,  off);
        sq += __shfl_down_sync(0xffffffffu, sq, off);
    }
    int wid = t >> 5, lane = t & 31;
    if (lane == 0) { red[wid*2] = s; red[wid*2+1] = sq; }
    __syncthreads();
    float S  = red[0] + red[2];
    float SQ = red[1] + red[3];
    float mean = S * (1.f/64.f);
    float var  = SQ * (1.f/64.f) - mean*mean;
    float rinv = rsqrtf(var + 1e-5f);
    ys[t] = (a - mean) * rinv * g2[t] + b2[t];
    __syncthreads();

    float h0 = bf1[t], h1 = bf1[t + 64];
    #pragma unroll 8
    for (int d = 0; d < 64; ++d) {
        float x = ys[d];
        h0 += x * Wf1[d*128 + t];
        h1 += x * Wf1[d*128 + t + 64];
    }
    hid[t]      = fmaxf(h0, 0.f);
    hid[t + 64] = fmaxf(h1, 0.f);
    __syncthreads();

    float o = a + bf2[t];
    #pragma unroll 8
    for (int c = 0; c < 128; ++c) o += hid[c] * Wf2[c*64 + t];
    out[row*64 + t] = o;
}

// ---------------- launch ----------------
extern "C" void kernel_launch(void* const* d_in, const int* in_sizes, int n_in,
                              void* d_out, int out_size)
{
    const float* h    = (const float*)d_in[0];
    const float* p    = (const float*)d_in[1];
    const float* e    = (const float*)d_in[2];
    const float* kRW  = (const float*)d_in[3];
    const float* mask = (const float*)d_in[4];
    const unsigned* adj = (const unsigned*)d_in[5];
    const float* WQ   = (const float*)d_in[6];
    const float* WK   = (const float*)d_in[7];
    const float* WV   = (const float*)d_in[8];
    const float* WQ2  = (const float*)d_in[9];
    const float* WK2  = (const float*)d_in[10];
    const float* WE   = (const float*)d_in[11];
    const float* WE2  = (const float*)d_in[12];
    const float* OW   = (const float*)d_in[13];
    const float* Ob   = (const float*)d_in[14];
    const float* g1   = (const float*)d_in[15];
    const float* b1   = (const float*)d_in[16];
    const float* g2   = (const float*)d_in[17];
    const float* b2   = (const float*)d_in[18];
    const float* Wf1  = (const float*)d_in[19];
    const float* bf1  = (const float*)d_in[20];
    const float* Wf2  = (const float*)d_in[21];
    const float* bf2  = (const float*)d_in[22];
    float* out = (float*)d_out;

    cudaFuncSetAttribute(k2_scores, cudaFuncAttributeMaxDynamicSharedMemorySize, K2_SMEM);
    cudaFuncSetAttribute(k4_att, cudaFuncAttributeMaxDynamicSharedMemorySize, 64*513*4);

    k0_init<<<1, 256>>>(WE2);
    k1_proj<<<NROWS, 64>>>(h, p, g1, b1, WQ, WK, WV, WQ2, WK2);
    k2_scores<<<NROWS, 128, K2_SMEM>>>(e, adj, WE);
    k4_att<<<dim3(64, BB), 256, 64*513*4>>>(kRW, mask);
    k5_out<<<NROWS, 64>>>(h, OW, Ob, g2, b2, Wf1, bf1, Wf2, bf2, out);
}

// round 7
// speedup vs baseline: 1.4269x; 1.4269x over previous
#include <cuda_runtime.h>
#include <cuda_bf16.h>
#include <math.h>
#include <stdint.h>

// Problem constants
#define BB 4
#define BN 512
#define BH 32
#define NROWS 2048

// ---------------- scratch (static device globals; no allocs) ----------------
__device__ float g_Q [NROWS*64];
__device__ float g_K [NROWS*64];   // pre-scaled by DH^-0.5
__device__ float g_VT[BB*64*BN];   // V transposed: [b][c][j]
__device__ float g_Q2[NROWS*64];
__device__ float g_K2[NROWS*64];   // pre-scaled
__device__ float g_WE2T[64*64];    // W_E2^T : [hk][d]
__device__ float g_scores[(size_t)BH*BN*BN];  // 33.5 MB
__device__ unsigned g_maxbits[BH];
__device__ float g_hatt[NROWS*64];

// ---------------- helpers ----------------
__device__ __forceinline__ void mma_bf16(float c[4],
    uint32_t a0, uint32_t a1, uint32_t a2, uint32_t a3,
    uint32_t b0, uint32_t b1)
{
    asm volatile(
        "mma.sync.aligned.m16n8k16.row.col.f32.bf16.bf16.f32 "
        "{%0,%1,%2,%3}, {%4,%5,%6,%7}, {%8,%9}, {%0,%1,%2,%3};"
        : "+f"(c[0]), "+f"(c[1]), "+f"(c[2]), "+f"(c[3])
        : "r"(a0), "r"(a1), "r"(a2), "r"(a3), "r"(b0), "r"(b1));
}
__device__ __forceinline__ unsigned f2key(float f) {
    unsigned u = __float_as_uint(f);
    return (u & 0x80000000u) ? ~u : (u | 0x80000000u);
}
__device__ __forceinline__ float key2f(unsigned key) {
    unsigned u = (key & 0x80000000u) ? (key ^ 0x80000000u) : ~key;
    return __uint_as_float(u);
}

// ---------------- K0: init max accumulators + transpose W_E2 ----------------
__global__ void __launch_bounds__(256) k0_init(const float* __restrict__ WE2) {
    int t = threadIdx.x;
    if (t < BH) g_maxbits[t] = 0u;  // key-space -inf
    for (int i = t; i < 4096; i += 256) {
        int d = i >> 6, c = i & 63;
        g_WE2T[c*64 + d] = WE2[i];
    }
}

// ---------------- K1: x = LN(h+p); Q,K,V,Q2,K2 projections ----------------
__global__ void __launch_bounds__(64) k1_proj(
    const float* __restrict__ h, const float* __restrict__ p,
    const float* __restrict__ g1, const float* __restrict__ b1,
    const float* __restrict__ WQ, const float* __restrict__ WK,
    const float* __restrict__ WV, const float* __restrict__ WQ2,
    const float* __restrict__ WK2)
{
    int row = blockIdx.x;
    int b = row >> 9, n = row & 511;
    int t = threadIdx.x;
    __shared__ float xs[64];
    __shared__ float red[4];

    float v = h[row*64 + t] + p[row*64 + t];
    float s = v, sq = v*v;
    #pragma unroll
    for (int off = 16; off; off >>= 1) {
        s  += __shfl_down_sync(0xffffffffu, s,  off);
        sq += __shfl_down_sync(0xffffffffu, sq, off);
    }
    int wid = t >> 5, lane = t & 31;
    if (lane == 0) { red[wid*2] = s; red[wid*2+1] = sq; }
    __syncthreads();
    float S  = red[0] + red[2];
    float SQ = red[1] + red[3];
    float mean = S * (1.f/64.f);
    float var  = SQ * (1.f/64.f) - mean*mean;
    float rinv = rsqrtf(var + 1e-5f);
    xs[t] = (v - mean) * rinv * g1[t] + b1[t];
    __syncthreads();

    float q = 0.f, k = 0.f, vv = 0.f, q2 = 0.f, k2 = 0.f;
    #pragma unroll 8
    for (int d = 0; d < 64; ++d) {
        float x = xs[d];
        q  += x * WQ [d*64 + t];
        k  += x * WK [d*64 + t];
        vv += x * WV [d*64 + t];
        q2 += x * WQ2[d*64 + t];
        k2 += x * WK2[d*64 + t];
    }
    const float sc = 0.35355339059327373f;  // 8^-0.5
    g_Q [row*64 + t] = q;
    g_K [row*64 + t] = k * sc;
    g_VT[((size_t)b*64 + t)*512 + n] = vv;
    g_Q2[row*64 + t] = q2;
    g_K2[row*64 + t] = k2 * sc;
}

// ---------------- K2: bf16 m16n8k16 tensor-core fused scores ----------------
// (round-5 proven version: 35KB smem, 5 CTAs/SM)
#define SMSB 72   // bf16 row stride for es/A2s (conflict-free)
#define SMSF 68   // fp32 row stride for K2s
__global__ void __launch_bounds__(128) k2_scores(
    const float* __restrict__ e, const unsigned* __restrict__ adj,
    const float* __restrict__ WE)
{
    extern __shared__ char dyn[];
    __nv_bfloat16* es  = (__nv_bfloat16*)dyn;                    // [64][SMSB] row=j, col=d
    __nv_bfloat16* A2s = (__nv_bfloat16*)(dyn + 64*SMSB*2);      // [64][SMSB] row=hk, col=d
    float*         K2s = (float*)        (dyn + 2*64*SMSB*2);    // [64][SMSF] row=j, col=hk

    __shared__ float qs[64], q2s[64];
    __shared__ int lst[64];
    __shared__ int cnt;
    __shared__ unsigned char adjf[64];

    int bi = blockIdx.x;
    int b = bi >> 9, i = bi & 511;
    int t = threadIdx.x;
    int w = t >> 5, lane = t & 31;
    int r = lane >> 2, cq = lane & 3;
    int m_base = w * 16;

    if (t < 64) qs[t] = g_Q[bi*64 + t];
    else        q2s[t-64] = g_Q2[bi*64 + (t-64)];
    __syncthreads();
    // A2s[hk][d] = W_E2^T[hk][d] * q2[hk], bf16
    #pragma unroll
    for (int it = 0; it < 16; ++it) {
        int idx = t + it*128;              // pair index, 2048 total
        int hk = idx >> 5, dp = idx & 31;
        float2 wv = *(const float2*)&g_WE2T[hk*64 + dp*2];
        float qv = q2s[hk];
        __nv_bfloat162 bv = __floats2bfloat162_rn(wv.x*qv, wv.y*qv);
        *(uint32_t*)&A2s[hk*SMSB + dp*2] = *(uint32_t*)&bv;
    }

    const float4* ebase  = (const float4*)(e + (size_t)bi * BN * 64);
    const float4* k2base = (const float4*)(g_K2 + (size_t)b * BN * 64);

    for (int jt = 0; jt < 8; ++jt) {
        int j0 = jt * 64;
        __syncthreads();       // prior tile fully consumed (also covers A2s build)
        if (t == 0) cnt = 0;
        // stage e tile (fp32 -> bf16) and K2 tile (fp32)
        #pragma unroll
        for (int it = 0; it < 8; ++it) {
            int idx = t + it*128;          // float4 index, 1024 total
            int jl = idx >> 4, c4 = idx & 15;
            float4 v = ebase[(size_t)(j0 + jl)*16 + c4];
            __nv_bfloat162 lo = __floats2bfloat162_rn(v.x, v.y);
            __nv_bfloat162 hi = __floats2bfloat162_rn(v.z, v.w);
            uint2 pk = { *(uint32_t*)&lo, *(uint32_t*)&hi };
            *(uint2*)&es[jl*SMSB + c4*4] = pk;
            float4 kv = k2base[(size_t)(j0 + jl)*16 + c4];
            *(float4*)&K2s[jl*SMSF + c4*4] = kv;
        }
        __syncthreads();       // cnt reset + tiles visible
        if (t < 64) {
            unsigned a = adj[(size_t)bi * BN + j0 + t];
            adjf[t] = a ? 1 : 0;
            if (a) { int pos = atomicAdd(&cnt, 1); lst[pos] = t; }
        }
        __syncthreads();       // list/flags ready

        // ---- dense E2 path: warp computes 16 rows x 64 hk, K=64 ----
        float acc[8][4];
        #pragma unroll
        for (int nt = 0; nt < 8; ++nt)
            #pragma unroll
            for (int z = 0; z < 4; ++z) acc[nt][z] = 0.f;

        int a_row0 = (m_base + r)*SMSB;
        int a_row1 = a_row0 + 8*SMSB;
        #pragma unroll
        for (int kc = 0; kc < 4; ++kc) {
            int k0 = kc*16 + cq*2;
            uint32_t a0 = *(const uint32_t*)&es[a_row0 + k0];
            uint32_t a1 = *(const uint32_t*)&es[a_row1 + k0];
            uint32_t a2 = *(const uint32_t*)&es[a_row0 + k0 + 8];
            uint32_t a3 = *(const uint32_t*)&es[a_row1 + k0 + 8];
            #pragma unroll
            for (int nt = 0; nt < 8; ++nt) {
                int n = nt*8 + r;
                uint32_t b0 = *(const uint32_t*)&A2s[n*SMSB + k0];
                uint32_t b1 = *(const uint32_t*)&A2s[n*SMSB + k0 + 8];
                mma_bf16(acc[nt], a0, a1, a2, a3, b0, b1);
            }
        }

        // ---- epilogue: score[h,j] = sum_k Y[j,h*8+k]*K2[j,h*8+k] ----
        int jl0 = m_base + r, jl1 = jl0 + 8;
        #pragma unroll
        for (int h = 0; h < 8; ++h) {
            float2 ka = *(const float2*)&K2s[jl0*SMSF + h*8 + 2*cq];
            float2 kb = *(const float2*)&K2s[jl1*SMSF + h*8 + 2*cq];
            float s0 = acc[h][0]*ka.x + acc[h][1]*ka.y;
            float s1 = acc[h][2]*kb.x + acc[h][3]*kb.y;
            s0 += __shfl_xor_sync(0xffffffffu, s0, 1);
            s0 += __shfl_xor_sync(0xffffffffu, s0, 2);
            s1 += __shfl_xor_sync(0xffffffffu, s1, 1);
            s1 += __shfl_xor_sync(0xffffffffu, s1, 2);
            if (cq == 0) {
                size_t srow = ((size_t)(b*8 + h)*BN + i)*BN + j0;
                if (!adjf[jl0]) g_scores[srow + jl0] = s0;
                if (!adjf[jl1]) g_scores[srow + jl1] = s1;
            }
        }

        // ---- sparse E path: one adj column per warp ----
        int n = cnt;
        for (int q = w; q < n; q += 4) {
            int jl = lst[q];
            int j = j0 + jl;
            float y0 = 0.f, y1 = 0.f;
            #pragma unroll 8
            for (int d = 0; d < 64; ++d) {
                float ev = __bfloat162float(es[jl*SMSB + d]);
                y0 += ev * WE[d*64 + lane];
                y1 += ev * WE[d*64 + 32 + lane];
            }
            y0 *= qs[lane];
            y1 *= qs[lane + 32];
            const float* kp = &g_K[((size_t)(b*BN + j))*64];
            float z0 = y0 * kp[lane];
            float z1 = y1 * kp[lane + 32];
            z0 += __shfl_xor_sync(0xffffffffu, z0, 1);
            z0 += __shfl_xor_sync(0xffffffffu, z0, 2);
            z0 += __shfl_xor_sync(0xffffffffu, z0, 4);
            z1 += __shfl_xor_sync(0xffffffffu, z1, 1);
            z1 += __shfl_xor_sync(0xffffffffu, z1, 2);
            z1 += __shfl_xor_sync(0xffffffffu, z1, 4);
            if ((lane & 7) == 0) {
                int h0 = lane >> 3;  // heads 0..3 (z0), 4..7 (z1)
                g_scores[((size_t)(b*8 + h0    )*BN + i)*BN + j] = z0;
                g_scores[((size_t)(b*8 + h0 + 4)*BN + i)*BN + j] = z1;
            }
        }
    }
}
#define K2_SMEM (2*64*SMSB*2 + 64*SMSF*4)   // 18432 + 17408 = 35840

// ---------------- K3: global max per (b,h) ----------------
__global__ void __launch_bounds__(256) k3_max() {
    int bh = blockIdx.x >> 4, ch = blockIdx.x & 15;
    const float4* base = (const float4*)(g_scores + (size_t)bh*BN*BN + (size_t)ch*16384);
    float m = -INFINITY;
    for (int idx = threadIdx.x; idx < 4096; idx += 256) {
        float4 v = base[idx];
        m = fmaxf(m, fmaxf(fmaxf(v.x, v.y), fmaxf(v.z, v.w)));
    }
    #pragma unroll
    for (int off = 16; off; off >>= 1) m = fmaxf(m, __shfl_xor_sync(0xffffffffu, m, off));
    __shared__ float red[8];
    if ((threadIdx.x & 31) == 0) red[threadIdx.x >> 5] = m;
    __syncthreads();
    if (threadIdx.x < 8) {
        float mm = red[threadIdx.x];
        mm = fmaxf(mm, __shfl_xor_sync(0x000000ffu, mm, 4));
        mm = fmaxf(mm, __shfl_xor_sync(0x000000ffu, mm, 2));
        mm = fmaxf(mm, __shfl_xor_sync(0x000000ffu, mm, 1));
        if (threadIdx.x == 0) atomicMax(&g_maxbits[bh], f2key(mm));
    }
}

// ---------------- K4: exp/mask/k_RW + rowsum + att@V (no V smem, VT in L2) ----
// One warp per (b,h,i). 8 warps/block, 2048 blocks; occupancy reg-limited only.
__global__ void __launch_bounds__(256) k4_att(
    const float* __restrict__ kRW, const float* __restrict__ mask)
{
    __shared__ float msk[512];
    int w = threadIdx.x >> 5, lane = threadIdx.x & 31;
    int g = blockIdx.x * 8 + w;          // 0..16383
    int b = g >> 12;
    int rem = g & 4095;
    int h = rem >> 9, i = rem & 511;

    for (int j = threadIdx.x; j < 512; j += 256) msk[j] = mask[b*512 + j];
    __syncthreads();

    float mx = key2f(g_maxbits[b*8 + h]);
    float mi = msk[i];
    const float* sp = g_scores + ((size_t)(b*8 + h)*512 + i)*512;
    const float* wp = kRW + ((size_t)(b*512 + i))*512;
    const float* vt = g_VT + ((size_t)(b*64) + h*8)*512;

    float pden = 0.f;
    float pav[8];
    #pragma unroll
    for (int k = 0; k < 8; ++k) pav[k] = 0.f;

    #pragma unroll 4
    for (int jt = 0; jt < 16; ++jt) {
        int j = jt*32 + lane;
        float pw = __expf(sp[j] - mx) * wp[j] * msk[j] * mi;
        pden += pw;
        #pragma unroll
        for (int k = 0; k < 8; ++k) pav[k] += pw * vt[k*512 + j];
    }
    #pragma unroll
    for (int off = 16; off; off >>= 1) {
        pden += __shfl_down_sync(0xffffffffu, pden, off);
        #pragma unroll
        for (int k = 0; k < 8; ++k) pav[k] += __shfl_down_sync(0xffffffffu, pav[k], off);
    }
    if (lane == 0) {
        float inv = 1.f / fmaxf(pden, 1e-6f);
        float4* op = (float4*)&g_hatt[((size_t)(b*512 + i))*64 + h*8];
        op[0] = make_float4(pav[0]*inv, pav[1]*inv, pav[2]*inv, pav[3]*inv);
        op[1] = make_float4(pav[4]*inv, pav[5]*inv, pav[6]*inv, pav[7]*inv);
    }
}

// ---------------- K5: O-proj + residual + LN2 + FFN + residual ----------------
__global__ void __launch_bounds__(64) k5_out(
    const float* __restrict__ hin, const float* __restrict__ OW,
    const float* __restrict__ Ob, const float* __restrict__ g2,
    const float* __restrict__ b2, const float* __restrict__ Wf1,
    const float* __restrict__ bf1, const float* __restrict__ Wf2,
    const float* __restrict__ bf2, float* __restrict__ out)
{
    int row = blockIdx.x;
    int t = threadIdx.x;
    __shared__ float has[64], ys[64], hid[128];
    __shared__ float red[4];

    has[t] = g_hatt[row*64 + t];
    __syncthreads();

    float a = hin[row*64 + t] + Ob[t];
    #pragma unroll 8
    for (int d = 0; d < 64; ++d) a += has[d] * OW[d*64 + t];

    float s = a, sq = a*a;
    #pragma unroll
    for (int off = 16; off; off >>= 1) {
        s  += __shfl_down_sync(0xffffffffu, s,  off);
        sq += __shfl_down_sync(0xffffffffu, sq, off);
    }
    int wid = t >> 5, lane = t & 31;
    if (lane == 0) { red[wid*2] = s; red[wid*2+1] = sq; }
    __syncthreads();
    float S  = red[0] + red[2];
    float SQ = red[1] + red[3];
    float mean = S * (1.f/64.f);
    float var  = SQ * (1.f/64.f) - mean*mean;
    float rinv = rsqrtf(var + 1e-5f);
    ys[t] = (a - mean) * rinv * g2[t] + b2[t];
    __syncthreads();

    float h0 = bf1[t], h1 = bf1[t + 64];
    #pragma unroll 8
    for (int d = 0; d < 64; ++d) {
        float x = ys[d];
        h0 += x * Wf1[d*128 + t];
        h1 += x * Wf1[d*128 + t + 64];
    }
    hid[t]      = fmaxf(h0, 0.f);
    hid[t + 64] = fmaxf(h1, 0.f);
    __syncthreads();

    float o = a + bf2[t];
    #pragma unroll 8
    for (int c = 0; c < 128; ++c) o += hid[c] * Wf2[c*64 + t];
    out[row*64 + t] = o;
}

// ---------------- launch ----------------
extern "C" void kernel_launch(void* const* d_in, const int* in_sizes, int n_in,
                              void* d_out, int out_size)
{
    const float* h    = (const float*)d_in[0];
    const float* p    = (const float*)d_in[1];
    const float* e    = (const float*)d_in[2];
    const float* kRW  = (const float*)d_in[3];
    const float* mask = (const float*)d_in[4];
    const unsigned* adj = (const unsigned*)d_in[5];
    const float* WQ   = (const float*)d_in[6];
    const float* WK   = (const float*)d_in[7];
    const float* WV   = (const float*)d_in[8];
    const float* WQ2  = (const float*)d_in[9];
    const float* WK2  = (const float*)d_in[10];
    const float* WE   = (const float*)d_in[11];
    const float* WE2  = (const float*)d_in[12];
    const float* OW   = (const float*)d_in[13];
    const float* Ob   = (const float*)d_in[14];
    const float* g1   = (const float*)d_in[15];
    const float* b1   = (const float*)d_in[16];
    const float* g2   = (const float*)d_in[17];
    const float* b2   = (const float*)d_in[18];
    const float* Wf1  = (const float*)d_in[19];
    const float* bf1  = (const float*)d_in[20];
    const float* Wf2  = (const float*)d_in[21];
    const float* bf2  = (const float*)d_in[22];
    float* out = (float*)d_out;

    cudaFuncSetAttribute(k2_scores, cudaFuncAttributeMaxDynamicSharedMemorySize, K2_SMEM);

    k0_init<<<1, 256>>>(WE2);
    k1_proj<<<NROWS, 64>>>(h, p, g1, b1, WQ, WK, WV, WQ2, WK2);
    k2_scores<<<NROWS, 128, K2_SMEM>>>(e, adj, WE);
    k3_max<<<BH*16, 256>>>();
    k4_att<<<2048, 256>>>(kRW, mask);
    k5_out<<<NROWS, 64>>>(h, OW, Ob, g2, b2, Wf1, bf1, Wf2, bf2, out);
}